// round 6
// baseline (speedup 1.0000x reference)
#include <cuda_runtime.h>

// ---------------- problem constants ----------------
#define BB      256
#define TT      50
#define IDD     16
#define NCV     32
#define D0V     512
#define DINV    528
#define HIDV    512
#define NSTEPS  5
#define DT_C    0.05f

#define HS      1056            // padded row stride of h (1040 used; pad stays zero)
#define G_CTAS  136             // 8 groups x 17 CTAs
#define NTHR    256

// ---------------- dynamic smem layout (floats) ----------------
// Wq: per k-pair kp, 16 quads {w_k(2c), w_k(2c+1), w_k1(2c), w_k1(2c+1)}
// W1: 272 kp x 64 ; W2: 256 kp x 64 ; W3: 256 kp x 64
// Xd: double buffer, per 32-k chunk: 16 kp x (32 rows x dup quad), kp stride 132
#define WS1_OFF 0
#define WS2_OFF (272 * 64)                    // 17408
#define WS3_OFF (WS2_OFF + 256 * 64)          // 33792
#define XD_OFF  (WS3_OFF + 256 * 64)          // 50176
#define XD_BUF  (16 * 132)                    // 2112 floats per chunk buffer
#define SMEM_FLOATS (XD_OFF + 2 * XD_BUF)     // 54400
#define SMEM_BYTES  (SMEM_FLOATS * 4)         // 217600 B (< 227KB opt-in)

// ---------------- device scratch (zero-initialized at module load) ----------
__device__ float g_h[2][BB * HS];
__device__ float g_a0[BB * HIDV];
__device__ float g_a1[BB * HIDV];
__device__ unsigned g_cnt[8 * 32];            // per-group barrier counters (128B apart)
__device__ unsigned g_gen[8 * 32];            // per-group generation (monotonic, wrap-safe)

// ---------------- scoped-atomic helpers ----------------
__device__ __forceinline__ unsigned ld_acq(const unsigned* p) {
    unsigned v;
    asm volatile("ld.acquire.gpu.u32 %0, [%1];" : "=r"(v) : "l"(p) : "memory");
    return v;
}
__device__ __forceinline__ void st_rel(unsigned* p, unsigned v) {
    asm volatile("st.release.gpu.u32 [%0], %1;" :: "l"(p), "r"(v) : "memory");
}
__device__ __forceinline__ unsigned atom_add_acqrel(unsigned* p, unsigned v) {
    unsigned o;
    asm volatile("atom.add.acq_rel.gpu.u32 %0, [%1], %2;" : "=r"(o) : "l"(p), "r"(v) : "memory");
    return o;
}

// ---------------- per-group barrier (17 CTAs, co-resident) ----------------
__device__ __forceinline__ void group_sync(int rb) {
    __syncthreads();
    if (threadIdx.x == 0) {
        const int s = rb * 32;
        unsigned gen = ld_acq(&g_gen[s]);
        if (atom_add_acqrel(&g_cnt[s], 1u) == 16u) {
            g_cnt[s] = 0u;                    // ordered before gen bump by st.release
            st_rel(&g_gen[s], gen + 1u);
        } else {
            while (ld_acq(&g_gen[s]) == gen) { }
        }
    }
    __syncthreads();
}

// ---------------- f32x2 helpers ----------------
__device__ __forceinline__ void ffma2_acc(unsigned long long& acc,
                                          unsigned long long a,
                                          unsigned long long b) {
    asm("fma.rn.f32x2 %0, %1, %2, %0;" : "+l"(acc) : "l"(a), "l"(b));
}
__device__ __forceinline__ void unpack2(unsigned long long v, float& lo, float& hi) {
    asm("mov.b64 {%0, %1}, %2;" : "=f"(lo), "=f"(hi) : "l"(v));
}

struct U2x2 { unsigned long long lo, hi; };
__device__ __forceinline__ U2x2 lds128_u2(const float* p) {
    U2x2 r;
    asm("ld.shared.v2.b64 {%0, %1}, [%2];"
        : "=l"(r.lo), "=l"(r.hi) : "l"((unsigned long long)__cvta_generic_to_shared(p)));
    return r;
}

// ---------------- GEMM phase: 32x32 tile, 256 threads, 2x2 per thread -------
// MODE 0/1: outbuf[row*512 + col] = relu(X@W + bias)
// MODE 2  : hn[row*HS + 512+col] = hc[row*HS + 512+col] + DT*(X@W + bias), col<528
template <int MODE>
__device__ __forceinline__ void gemm_phase(const float* __restrict__ X, int xs, int nkc,
                                           const float* __restrict__ Wq,
                                           const float* __restrict__ bias,
                                           float* __restrict__ outbuf,
                                           const float* __restrict__ hc,
                                           float* __restrict__ hn,
                                           float* __restrict__ Xd,
                                           int r0, int c0) {
    const int tid = threadIdx.x;
    // loader: warp = one k-quad kq (0..7), lanes = 32 rows
    const int lrow = tid & 31;
    const int lkq  = tid >> 5;
    // compute: warp w: wr=w>>2 (row half), wc=w&3 (col block); lane: lrp=l&7, lc=l>>3
    const int w = tid >> 5, l = tid & 31;
    const int wr = w >> 2, wc = w & 3;
    const int lrp = l & 7, lc = l >> 3;
    const int rA = wr * 16 + lrp;         // row A (0..31)
    const int rB = rA + 8;                // row B
    const int cp = wc * 4 + lc;           // col-pair 0..15 -> cols 2cp, 2cp+1

    const float* xsrc = X + (r0 + lrow) * xs + 4 * lkq;

    unsigned long long aA = 0ull, aB = 0ull;   // {o(r,2cp), o(r,2cp+1)} for rA / rB

    float4 pre = *(const float4*)(xsrc);
    {
        float* d = Xd;
        *(float4*)(d + (2 * lkq + 0) * 132 + lrow * 4) = make_float4(pre.x, pre.x, pre.y, pre.y);
        *(float4*)(d + (2 * lkq + 1) * 132 + lrow * 4) = make_float4(pre.z, pre.z, pre.w, pre.w);
    }
    if (nkc > 1) pre = *(const float4*)(xsrc + 32);
    __syncthreads();

    for (int kc = 0; kc < nkc; kc++) {
        if (kc + 1 < nkc) {
            float* d = Xd + ((kc + 1) & 1) * XD_BUF;
            *(float4*)(d + (2 * lkq + 0) * 132 + lrow * 4) = make_float4(pre.x, pre.x, pre.y, pre.y);
            *(float4*)(d + (2 * lkq + 1) * 132 + lrow * 4) = make_float4(pre.z, pre.z, pre.w, pre.w);
        }
        if (kc + 2 < nkc) pre = *(const float4*)(xsrc + (kc + 2) * 32);

        const float* xb = Xd + (kc & 1) * XD_BUF;
        const float* wb = Wq + kc * (16 * 64) + cp * 4;
        #pragma unroll
        for (int kp = 0; kp < 16; kp++) {
            U2x2 x0 = lds128_u2(xb + kp * 132 + rA * 4);   // {xk(rA) dup | xk1(rA) dup}
            U2x2 x1 = lds128_u2(xb + kp * 132 + rB * 4);
            U2x2 wv = lds128_u2(wb + kp * 64);             // {wk(c0,c1) | wk1(c0,c1)}
            ffma2_acc(aA, x0.lo, wv.lo);
            ffma2_acc(aA, x0.hi, wv.hi);
            ffma2_acc(aB, x1.lo, wv.lo);
            ffma2_acc(aB, x1.hi, wv.hi);
        }
        __syncthreads();
    }

    float oA0, oA1, oB0, oB1;
    unpack2(aA, oA0, oA1);
    unpack2(aB, oB0, oB1);

    const int gra = r0 + rA, grb = r0 + rB;
    const int ca = c0 + 2 * cp;
    if (MODE != 2) {
        float2 bv = *(const float2*)&bias[ca];
        *(float2*)&outbuf[gra * 512 + ca] = make_float2(fmaxf(oA0 + bv.x, 0.f), fmaxf(oA1 + bv.y, 0.f));
        *(float2*)&outbuf[grb * 512 + ca] = make_float2(fmaxf(oB0 + bv.x, 0.f), fmaxf(oB1 + bv.y, 0.f));
    } else {
        if (ca < DINV) {
            float2 bv = *(const float2*)&bias[ca];
            float2 h0 = *(const float2*)&hc[gra * HS + 512 + ca];
            float2 h1 = *(const float2*)&hc[grb * HS + 512 + ca];
            *(float2*)&hn[gra * HS + 512 + ca] =
                make_float2(h0.x + DT_C * (oA0 + bv.x), h0.y + DT_C * (oA1 + bv.y));
            *(float2*)&hn[grb * HS + 512 + ca] =
                make_float2(h1.x + DT_C * (oB0 + bv.x), h1.y + DT_C * (oB1 + bv.y));
        }
    }
}

// ---------------- cn0 ODE phase (j==16 CTA; A/Bv cached in its W1 region) ----
__device__ __forceinline__ void cnode_phase(int rb,
                                            const float* __restrict__ hc,
                                            float* __restrict__ hn,
                                            const float* __restrict__ As,
                                            const float* __restrict__ Bs) {
    const int tid = threadIdx.x;
    const int b0 = rb * 32;
    #pragma unroll
    for (int rep = 0; rep < 2; rep++) {
        const int item = rep * NTHR + tid;      // 0..511
        const int b = b0 + (item >> 4);
        const int i = item & 15;
        const float* hr = hc + b * HS;
        float x[32];
        const float4* cpp = (const float4*)(hr + i * 32);
        #pragma unroll
        for (int q = 0; q < 8; q++) {
            float4 v = cpp[q];
            x[4 * q] = v.x; x[4 * q + 1] = v.y; x[4 * q + 2] = v.z; x[4 * q + 3] = v.w;
        }
        const float cn1v = hr[512 + i];
        float* outp = hn + b * HS + i * 32;
        #pragma unroll 4
        for (int n = 0; n < 32; n++) {
            float acc = Bs[n] * cn1v;
            const float4* ap = (const float4*)(As + n * 32);
            #pragma unroll
            for (int q = 0; q < 8; q++) {
                float4 a4 = ap[q];
                acc = fmaf(x[4 * q], a4.x, acc);
                acc = fmaf(x[4 * q + 1], a4.y, acc);
                acc = fmaf(x[4 * q + 2], a4.z, acc);
                acc = fmaf(x[4 * q + 3], a4.w, acc);
            }
            outp[n] = x[n] + DT_C * acc;
        }
    }
}

// ---------------- observation update (group-local) ----------------
__device__ __forceinline__ void obs_phase(int rb, int j, int t,
                                          const float* __restrict__ Y,
                                          const float* __restrict__ mask,
                                          float* __restrict__ h,
                                          float* __restrict__ out,
                                          long off_traj, long off_lasth, int tlast) {
    const int gid = j * NTHR + threadIdx.x;
    const int nth = 17 * NTHR;
    const int b0 = rb * 32;
    for (int idx = gid; idx < 32 * DINV; idx += nth) {
        const int b = b0 + idx / DINV;
        const int c = idx % DINV;
        const float m = mask[b * TT + t];
        float* hr = h + b * HS;
        const float he = hr[512 + c];
        if (c < IDD) {
            const long po = (long)(b * TT + t) * IDD + c;
            out[po] = he;
            if (off_traj >= 0) out[off_traj + po] = he;
            const float y = Y[(b * TT + t) * IDD + c];
            hr[512 + c] = m * y + (1.f - m) * he;
        } else {
            const int jj = c - IDD;
            hr[512 + c] = m * hr[jj] + (1.f - m) * he;
        }
    }
    if (t == tlast) {
        for (int idx = gid; idx < 32 * D0V; idx += nth) {
            const int b = b0 + (idx >> 9);
            const int jj = idx & 511;
            out[off_lasth + (long)b * D0V + jj] = h[b * HS + jj];
        }
    }
}

// ---------------- single persistent kernel ----------------
__global__ void __launch_bounds__(NTHR, 1)
cnode_persistent(const float* __restrict__ times,
                 const float* __restrict__ Y, const float* __restrict__ mask,
                 const float* __restrict__ A, const float* __restrict__ Bv,
                 const float* __restrict__ W1, const float* __restrict__ b1,
                 const float* __restrict__ W2, const float* __restrict__ b2,
                 const float* __restrict__ W3, const float* __restrict__ b3,
                 float* __restrict__ out,
                 long off_traj, long off_times, long off_lasth, long off_hfin) {
    extern __shared__ float sm[];
    __shared__ int s_tl;
    const int cta = blockIdx.x;
    const int tid = threadIdx.x;
    const int rb = cta / 17;          // row block 0..7 (batch rows rb*32..+31)
    const int j  = cta - rb * 17;     // 0..16
    const int r0 = rb * 32;
    const int c0 = j * 32;            // col tile origin (j==16 -> 512, GEMM3 only)

    // ---- prologue: tlast (redundant per CTA), h zero, out init ----
    if (tid == 0) s_tl = -1;
    __syncthreads();
    {
        int local = -1;
        for (int idx = tid; idx < BB * TT; idx += NTHR)
            if (mask[idx] > 0.f) { int t = idx % TT; if (t > local) local = t; }
        if (local >= 0) atomicMax(&s_tl, local);
    }
    // zero this group's h rows (both buffers, full padded stride)
    {
        const int gid = j * NTHR + tid;
        const int nth = 17 * NTHR;
        for (int idx = gid; idx < 32 * HS; idx += nth) {
            const int b = r0 + idx / HS;
            const int c = idx % HS;
            g_h[0][b * HS + c] = 0.f;
            g_h[1][b * HS + c] = 0.f;
        }
        for (int idx = gid; idx < 32 * D0V; idx += nth)
            out[off_lasth + (long)r0 * D0V + idx] = 0.f;
    }
    if (cta == 0 && tid < TT) out[off_times + tid] = times[tid];

    // ---- load resident weights (k-paired quad layout) ----
    if (j < 16) {
        for (int idx = tid; idx < 272 * 64; idx += NTHR) {
            const int kp = idx >> 6, r = idx & 63;
            const int tcq = r >> 2, e = r & 3;
            const int k = 2 * kp + (e >> 1);
            const int c = c0 + 2 * tcq + (e & 1);
            sm[WS1_OFF + idx] = (k < DINV) ? W1[k * HIDV + c] : 0.f;
        }
        for (int idx = tid; idx < 256 * 64; idx += NTHR) {
            const int kp = idx >> 6, r = idx & 63;
            const int tcq = r >> 2, e = r & 3;
            const int k = 2 * kp + (e >> 1);
            const int c = c0 + 2 * tcq + (e & 1);
            sm[WS2_OFF + idx] = W2[k * HIDV + c];
        }
    } else {
        for (int i = tid; i < NCV * NCV; i += NTHR) sm[WS1_OFF + i] = A[i];
        for (int i = tid; i < NCV; i += NTHR) sm[WS1_OFF + 1024 + i] = Bv[i];
    }
    for (int idx = tid; idx < 256 * 64; idx += NTHR) {
        const int kp = idx >> 6, r = idx & 63;
        const int tcq = r >> 2, e = r & 3;
        const int k = 2 * kp + (e >> 1);
        const int c = c0 + 2 * tcq + (e & 1);
        sm[WS3_OFF + idx] = (c < DINV) ? W3[k * DINV + c] : 0.f;
    }
    __syncthreads();
    const int tlast = s_tl;
    group_sync(rb);                    // h zeroing visible group-wide

    float* Xd = sm + XD_OFF;

    int cur = 0;
    for (int t = 0; t < TT; t++) {
        for (int s = 0; s < NSTEPS; s++) {
            float* hc = g_h[cur];
            float* hn = g_h[cur ^ 1];
            // phase 1: GEMM1 (K=544 padded, 17 chunks) on j<16 ; cn_ode on j==16
            if (j < 16)
                gemm_phase<0>(hc + 512, HS, 17, sm + WS1_OFF, b1, g_a0,
                              nullptr, nullptr, Xd, r0, c0);
            else
                cnode_phase(rb, hc, hn, sm + WS1_OFF, sm + WS1_OFF + 1024);
            group_sync(rb);
            // phase 2: GEMM2 (K=512)
            if (j < 16)
                gemm_phase<1>(g_a0, HIDV, 16, sm + WS2_OFF, b2, g_a1,
                              nullptr, nullptr, Xd, r0, c0);
            group_sync(rb);
            // phase 3: GEMM3 (K=512) + euler update of cn1 part (all 17)
            gemm_phase<2>(g_a1, HIDV, 16, sm + WS3_OFF, b3, nullptr,
                          hc, hn, Xd, r0, c0);
            group_sync(rb);
            cur ^= 1;
        }
        obs_phase(rb, j, t, Y, mask, g_h[cur], out, off_traj, off_lasth, tlast);
        group_sync(rb);
    }
    // h_fin copy (group-local rows)
    const int gid = j * NTHR + tid;
    const float* h = g_h[cur];
    for (int idx = gid; idx < 32 * 1040; idx += 17 * NTHR) {
        const int b = r0 + idx / 1040;
        const int c = idx % 1040;
        out[off_hfin + (long)b * 1040 + c] = h[b * HS + c];
    }
}

// ---------------- launch ----------------
extern "C" void kernel_launch(void* const* d_in, const int* in_sizes, int n_in,
                              void* d_out, int out_size) {
    const float* times = (const float*)d_in[0];
    const float* Y     = (const float*)d_in[1];
    const float* mask  = (const float*)d_in[2];
    const float* A     = (const float*)d_in[3];
    const float* Bv    = (const float*)d_in[4];
    const float* W1    = (const float*)d_in[5];
    const float* b1    = (const float*)d_in[6];
    const float* W2    = (const float*)d_in[7];
    const float* b2    = (const float*)d_in[8];
    const float* W3    = (const float*)d_in[9];
    const float* b3    = (const float*)d_in[10];
    float* out = (float*)d_out;

    cudaFuncSetAttribute(cnode_persistent,
                         cudaFuncAttributeMaxDynamicSharedMemorySize, SMEM_BYTES);

    const long np = (long)BB * TT * IDD;          // 204800
    long off_traj, off_times, off_lasth, off_hfin;
    const long full = 2 * np + TT + (long)BB * D0V + (long)BB * (2 * D0V + IDD);
    if ((long)out_size >= full) {
        off_traj = np;
        off_times = 2 * np;
    } else {
        off_traj = -1;
        off_times = np;
    }
    off_lasth = off_times + TT;
    off_hfin = off_lasth + (long)BB * D0V;

    cnode_persistent<<<G_CTAS, NTHR, SMEM_BYTES>>>(times, Y, mask, A, Bv,
                                                   W1, b1, W2, b2, W3, b3,
                                                   out, off_traj, off_times,
                                                   off_lasth, off_hfin);
}

// round 8
// speedup vs baseline: 1.4725x; 1.4725x over previous
#include <cuda_runtime.h>

typedef unsigned long long ull;

#define BB 256
#define TT 50
#define IDD 16
#define NCV 32
#define D0V 512
#define DINV 528
#define HIDV 512
#define NSTEPS 5
#define DT_C 0.05f
#define HS 1056
#define G_CTAS 136
#define NTHR 256

// smem layout (floats): W k-major stride 33; X double-buffered 64-k chunks stride 38
#define WS1_OFF 0
#define WS2_OFF (544 * 33)                 // 17952
#define WS3_OFF (WS2_OFF + 512 * 33)       // 34848
#define XD_OFF  (WS3_OFF + 512 * 33)       // 51744
#define XD_BUF  (64 * 38)                  // 2432
#define SMEM_FLOATS (XD_OFF + 2 * XD_BUF)  // 56608
#define SMEM_BYTES  (SMEM_FLOATS * 4)      // 226432 B

__device__ float g_h[2][BB * HS];
__device__ float g_a0[BB * HIDV];
__device__ float g_a1[BB * HIDV];
__device__ unsigned g_cnt[8 * 32];
__device__ unsigned g_gen[8 * 32];

__device__ __forceinline__ unsigned ld_acq(const unsigned* p) {
    unsigned v; asm volatile("ld.acquire.gpu.u32 %0, [%1];" : "=r"(v) : "l"(p) : "memory"); return v;
}
__device__ __forceinline__ void st_rel(unsigned* p, unsigned v) {
    asm volatile("st.release.gpu.u32 [%0], %1;" :: "l"(p), "r"(v) : "memory");
}
__device__ __forceinline__ unsigned atom_add_acqrel(unsigned* p, unsigned v) {
    unsigned o; asm volatile("atom.add.acq_rel.gpu.u32 %0, [%1], %2;" : "=r"(o) : "l"(p), "r"(v) : "memory"); return o;
}

__device__ __forceinline__ void group_sync(int rb) {
    __syncthreads();
    if (threadIdx.x == 0) {
        const int s = rb * 32;
        unsigned gen = ld_acq(&g_gen[s]);
        if (atom_add_acqrel(&g_cnt[s], 1u) == 16u) {
            g_cnt[s] = 0u;
            st_rel(&g_gen[s], gen + 1u);
        } else {
            while (ld_acq(&g_gen[s]) == gen) { }
        }
    }
    __syncthreads();
}

__device__ __forceinline__ void ffma2_acc(ull& acc, ull a, ull b) {
    asm("fma.rn.f32x2 %0, %1, %2, %0;" : "+l"(acc) : "l"(a), "l"(b));
}
__device__ __forceinline__ ull add2(ull a, ull b) {
    ull d; asm("add.rn.f32x2 %0, %1, %2;" : "=l"(d) : "l"(a), "l"(b)); return d;
}
__device__ __forceinline__ ull splat2(float x) {
    ull v; asm("mov.b64 %0, {%1, %1};" : "=l"(v) : "f"(x)); return v;
}
__device__ __forceinline__ void unpack2(ull v, float& lo, float& hi) {
    asm("mov.b64 {%0, %1}, %2;" : "=f"(lo), "=f"(hi) : "l"(v));
}
__device__ __forceinline__ ull lds64(const float* p) {
    ull v; asm("ld.shared.b64 %0, [%1];" : "=l"(v) : "l"((ull)__cvta_generic_to_shared(p))); return v;
}

__device__ __forceinline__ void xstore(float* d, float4 q, int kofs, int lq, int lr) {
    d[(kofs + 4 * lq + 0) * 38 + lr] = q.x;
    d[(kofs + 4 * lq + 1) * 38 + lr] = q.y;
    d[(kofs + 4 * lq + 2) * 38 + lr] = q.z;
    d[(kofs + 4 * lq + 3) * 38 + lr] = q.w;
}

// ---- K-split GEMM: 32x32 tile; tid = s*16+kg; thread = 8x8 outputs, K-slice kg mod 16
// MODE 0/1: outbuf[row*512+col] = relu(v + bias) ; MODE 2: hn = hc + DT*(v+bias), col<528
template <int MODE>
__device__ __forceinline__ void gemm_ks(const float* __restrict__ X, int xs, int Kt,
                                        const float* __restrict__ Wsm,
                                        const float* __restrict__ bias,
                                        float* __restrict__ outbuf,
                                        const float* __restrict__ hc,
                                        float* __restrict__ hn,
                                        float* __restrict__ Xs, int r0, int c0) {
    const int tid = threadIdx.x;
    const int s = tid >> 4, kg = tid & 15;
    const int sr = s >> 2, sc = s & 3;
    const int lr = tid >> 3, lq = tid & 7;

    ull acc[32];                      // flat a*8+c: rows (8sr+2a, +1), col 8sc+c
    #pragma unroll
    for (int i = 0; i < 32; i++) acc[i] = 0ull;

    const int nch = (Kt + 63) >> 6;
    const float* xr = X + (r0 + lr) * xs;

    float4 pa, pb;
    pa = *(const float4*)(xr + 4 * lq);                       // chunk 0 (always full)
    pb = *(const float4*)(xr + 32 + 4 * lq);
    xstore(Xs, pa, 0, lq, lr);
    xstore(Xs, pb, 32, lq, lr);
    if (nch > 1) {
        pa = *(const float4*)(xr + 64 + 4 * lq);
        if (Kt - 64 > 32) pb = *(const float4*)(xr + 96 + 4 * lq);
    }
    __syncthreads();

    for (int ch = 0; ch < nch; ch++) {
        if (ch + 1 < nch) {
            float* d = Xs + ((ch + 1) & 1) * XD_BUF;
            xstore(d, pa, 0, lq, lr);
            if (Kt - 64 * (ch + 1) > 32) xstore(d, pb, 32, lq, lr);
        }
        if (ch + 2 < nch) {
            const int kb = 64 * (ch + 2);
            pa = *(const float4*)(xr + kb + 4 * lq);
            if (Kt - kb > 32) pb = *(const float4*)(xr + kb + 32 + 4 * lq);
        }
        const float* xb = Xs + (ch & 1) * XD_BUF + 8 * sr;
        const float* wb = Wsm + (64 * ch) * 33 + 8 * sc;
        const int iters = ((Kt - 64 * ch) < 64 ? (Kt - 64 * ch) : 64) >> 4;
        #pragma unroll 4
        for (int ii = 0; ii < iters; ii++) {
            const int kl = kg + (ii << 4);
            const float* xp = xb + kl * 38;
            const float* wp = wb + kl * 33;
            ull x0 = lds64(xp), x1 = lds64(xp + 2), x2 = lds64(xp + 4), x3 = lds64(xp + 6);
            #pragma unroll
            for (int c = 0; c < 8; c++) {
                ull wd = splat2(wp[c]);
                ffma2_acc(acc[c],      x0, wd);
                ffma2_acc(acc[8 + c],  x1, wd);
                ffma2_acc(acc[16 + c], x2, wd);
                ffma2_acc(acc[24 + c], x3, wd);
            }
        }
        __syncthreads();
    }

    // ---- butterfly reduce over kg (lane bits 0..3) ----
    #pragma unroll
    for (int rnd = 0; rnd < 4; rnd++) {
        const int m = 1 << rnd;
        const int half = 16 >> rnd;
        const bool hi = (kg & m) != 0;
        #pragma unroll
        for (int i = 0; i < half; i++) {
            ull send = hi ? acc[i] : acc[i + half];
            ull other = __shfl_xor_sync(0xffffffffu, send, m);
            ull keep = hi ? acc[i + half] : acc[i];
            acc[i] = add2(keep, other);
        }
    }
    const int rkg = ((kg & 1) << 3) | ((kg & 2) << 1) | ((kg & 4) >> 1) | ((kg & 8) >> 3);
    #pragma unroll
    for (int u = 0; u < 2; u++) {
        const int f = 2 * rkg + u;
        const int a = f >> 3, c = f & 7;
        float v0, v1; unpack2(acc[u], v0, v1);
        const int row = r0 + 8 * sr + 2 * a;
        const int cg = c0 + 8 * sc + c;
        if (MODE != 2) {
            const float bv = bias[cg];
            outbuf[row * 512 + cg] = fmaxf(v0 + bv, 0.f);
            outbuf[(row + 1) * 512 + cg] = fmaxf(v1 + bv, 0.f);
        } else if (cg < DINV) {
            const float bv = bias[cg];
            const long i0 = (long)row * HS + 512 + cg;
            hn[i0] = hc[i0] + DT_C * (v0 + bv);
            hn[i0 + HS] = hc[i0 + HS] + DT_C * (v1 + bv);
        }
    }
}

// ---- cn0 ODE phase (j==16 CTA; A/Bv cached in its free W1 smem) ----
__device__ __forceinline__ void cnode_phase(int rb, const float* __restrict__ hc,
                                            float* __restrict__ hn,
                                            const float* __restrict__ As,
                                            const float* __restrict__ Bs) {
    const int tid = threadIdx.x;
    const int b0 = rb * 32;
    #pragma unroll
    for (int rep = 0; rep < 2; rep++) {
        const int item = rep * NTHR + tid;
        const int b = b0 + (item >> 4);
        const int i = item & 15;
        const float* hr = hc + b * HS;
        float x[32];
        const float4* cpp = (const float4*)(hr + i * 32);
        #pragma unroll
        for (int q = 0; q < 8; q++) {
            float4 v = cpp[q];
            x[4 * q] = v.x; x[4 * q + 1] = v.y; x[4 * q + 2] = v.z; x[4 * q + 3] = v.w;
        }
        const float cn1v = hr[512 + i];
        float* outp = hn + b * HS + i * 32;
        #pragma unroll 4
        for (int n = 0; n < 32; n++) {
            float acc = Bs[n] * cn1v;
            const float4* ap = (const float4*)(As + n * 32);
            #pragma unroll
            for (int q = 0; q < 8; q++) {
                float4 a4 = ap[q];
                acc = fmaf(x[4 * q], a4.x, acc);
                acc = fmaf(x[4 * q + 1], a4.y, acc);
                acc = fmaf(x[4 * q + 2], a4.z, acc);
                acc = fmaf(x[4 * q + 3], a4.w, acc);
            }
            outp[n] = x[n] + DT_C * acc;
        }
    }
}

__device__ __forceinline__ void obs_phase(int rb, int j, int t,
                                          const float* __restrict__ Y,
                                          const float* __restrict__ mask,
                                          float* __restrict__ h, float* __restrict__ out,
                                          long off_traj, long off_lasth, int tlast) {
    const int gid = j * NTHR + threadIdx.x;
    const int nth = 17 * NTHR;
    const int b0 = rb * 32;
    for (int idx = gid; idx < 32 * DINV; idx += nth) {
        const int b = b0 + idx / DINV;
        const int c = idx % DINV;
        const float m = mask[b * TT + t];
        float* hr = h + b * HS;
        const float he = hr[512 + c];
        if (c < IDD) {
            const long po = (long)(b * TT + t) * IDD + c;
            out[po] = he;
            if (off_traj >= 0) out[off_traj + po] = he;
            const float y = Y[(b * TT + t) * IDD + c];
            hr[512 + c] = m * y + (1.f - m) * he;
        } else {
            hr[512 + c] = m * hr[c - IDD] + (1.f - m) * he;
        }
    }
    if (t == tlast) {
        for (int idx = gid; idx < 32 * D0V; idx += nth) {
            const int b = b0 + (idx >> 9);
            const int jj = idx & 511;
            out[off_lasth + (long)b * D0V + jj] = h[b * HS + jj];
        }
    }
}

__global__ void __launch_bounds__(NTHR, 1)
cnode_persistent(const float* __restrict__ times,
                 const float* __restrict__ Y, const float* __restrict__ mask,
                 const float* __restrict__ A, const float* __restrict__ Bv,
                 const float* __restrict__ W1, const float* __restrict__ b1,
                 const float* __restrict__ W2, const float* __restrict__ b2,
                 const float* __restrict__ W3, const float* __restrict__ b3,
                 float* __restrict__ out,
                 long off_traj, long off_times, long off_lasth, long off_hfin) {
    extern __shared__ float sm[];
    __shared__ int s_tl;
    const int cta = blockIdx.x;
    const int tid = threadIdx.x;
    const int rb = cta / 17;
    const int j  = cta - rb * 17;
    const int r0 = rb * 32;
    const int c0 = j * 32;

    if (tid == 0) s_tl = -1;
    __syncthreads();
    {
        int local = -1;
        for (int idx = tid; idx < BB * TT; idx += NTHR)
            if (mask[idx] > 0.f) { int t = idx % TT; if (t > local) local = t; }
        if (local >= 0) atomicMax(&s_tl, local);
    }
    {
        const int gid = j * NTHR + tid;
        const int nth = 17 * NTHR;
        for (int idx = gid; idx < 32 * HS; idx += nth) {
            const int b = r0 + idx / HS, c = idx % HS;
            g_h[0][b * HS + c] = 0.f;
            g_h[1][b * HS + c] = 0.f;
        }
        for (int idx = gid; idx < 32 * D0V; idx += nth)
            out[off_lasth + (long)r0 * D0V + idx] = 0.f;
    }
    if (cta == 0 && tid < TT) out[off_times + tid] = times[tid];

    // resident weights, k-major stride 33
    if (j < 16) {
        for (int idx = tid; idx < 544 * 32; idx += NTHR) {
            const int k = idx >> 5, lc = idx & 31;
            sm[WS1_OFF + k * 33 + lc] = (k < DINV) ? W1[k * HIDV + c0 + lc] : 0.f;
        }
        for (int idx = tid; idx < 512 * 32; idx += NTHR) {
            const int k = idx >> 5, lc = idx & 31;
            sm[WS2_OFF + k * 33 + lc] = W2[k * HIDV + c0 + lc];
        }
    } else {
        for (int i = tid; i < NCV * NCV; i += NTHR) sm[WS1_OFF + i] = A[i];
        for (int i = tid; i < NCV; i += NTHR) sm[WS1_OFF + 1024 + i] = Bv[i];
    }
    for (int idx = tid; idx < 512 * 32; idx += NTHR) {
        const int k = idx >> 5, lc = idx & 31;
        const int c = c0 + lc;
        sm[WS3_OFF + k * 33 + lc] = (c < DINV) ? W3[k * DINV + c] : 0.f;
    }
    __syncthreads();
    const int tlast = s_tl;
    group_sync(rb);

    float* Xd = sm + XD_OFF;
    int cur = 0;
    for (int t = 0; t < TT; t++) {
        for (int s = 0; s < NSTEPS; s++) {
            float* hc = g_h[cur];
            float* hn = g_h[cur ^ 1];
            if (j < 16)
                gemm_ks<0>(hc + 512, HS, 544, sm + WS1_OFF, b1, g_a0, 0, 0, Xd, r0, c0);
            else
                cnode_phase(rb, hc, hn, sm + WS1_OFF, sm + WS1_OFF + 1024);
            group_sync(rb);
            if (j < 16)
                gemm_ks<1>(g_a0, HIDV, 512, sm + WS2_OFF, b2, g_a1, 0, 0, Xd, r0, c0);
            group_sync(rb);
            gemm_ks<2>(g_a1, HIDV, 512, sm + WS3_OFF, b3, 0, hc, hn, Xd, r0, c0);
            group_sync(rb);
            cur ^= 1;
        }
        obs_phase(rb, j, t, Y, mask, g_h[cur], out, off_traj, off_lasth, tlast);
        group_sync(rb);
    }
    const int gid = j * NTHR + tid;
    const float* h = g_h[cur];
    for (int idx = gid; idx < 32 * 1040; idx += 17 * NTHR) {
        const int b = r0 + idx / 1040, c = idx % 1040;
        out[off_hfin + (long)b * 1040 + c] = h[b * HS + c];
    }
}

extern "C" void kernel_launch(void* const* d_in, const int* in_sizes, int n_in,
                              void* d_out, int out_size) {
    const float* times = (const float*)d_in[0];
    const float* Y     = (const float*)d_in[1];
    const float* mask  = (const float*)d_in[2];
    const float* A     = (const float*)d_in[3];
    const float* Bv    = (const float*)d_in[4];
    const float* W1    = (const float*)d_in[5];
    const float* b1    = (const float*)d_in[6];
    const float* W2    = (const float*)d_in[7];
    const float* b2    = (const float*)d_in[8];
    const float* W3    = (const float*)d_in[9];
    const float* b3    = (const float*)d_in[10];
    float* out = (float*)d_out;

    cudaFuncSetAttribute(cnode_persistent,
                         cudaFuncAttributeMaxDynamicSharedMemorySize, SMEM_BYTES);

    const long np = (long)BB * TT * IDD;
    long off_traj, off_times, off_lasth, off_hfin;
    const long full = 2 * np + TT + (long)BB * D0V + (long)BB * (2 * D0V + IDD);
    if ((long)out_size >= full) { off_traj = np; off_times = 2 * np; }
    else { off_traj = -1; off_times = np; }
    off_lasth = off_times + TT;
    off_hfin = off_lasth + (long)BB * D0V;

    cnode_persistent<<<G_CTAS, NTHR, SMEM_BYTES>>>(times, Y, mask, A, Bv,
                                                   W1, b1, W2, b2, W3, b3,
                                                   out, off_traj, off_times,
                                                   off_lasth, off_hfin);
}